// round 9
// baseline (speedup 1.0000x reference)
#include <cuda_runtime.h>
#include <cuda_fp16.h>
#include <stdint.h>

#define B_ 4
#define N_ 1024
#define D_ 64
#define NN (B_ * N_ * N_)
#define NPAIRS 528
#define NUNITS (NPAIRS * B_)   // 2112

typedef unsigned long long ull;

// Scratch (device globals — no allocation allowed)
__device__ float g_hs[B_ * N_ * D_];
__device__ float g_hd[B_ * N_ * D_];
__device__ float g_ths[B_ * N_];
__device__ float g_thd[B_ * N_];

// ---------------------------------------------------------------------------
// f32x2 packed helpers (sm_103a)
// ---------------------------------------------------------------------------
__device__ __forceinline__ ull add2(ull a, ull b) {
    ull r; asm("add.rn.f32x2 %0, %1, %2;" : "=l"(r) : "l"(a), "l"(b)); return r;
}
__device__ __forceinline__ ull fma2(ull a, ull b, ull c) {
    ull r; asm("fma.rn.f32x2 %0, %1, %2, %3;" : "=l"(r) : "l"(a), "l"(b), "l"(c)); return r;
}
__device__ __forceinline__ ull pack2(float v) {
    ull r; unsigned u = __float_as_uint(v);
    asm("mov.b64 %0, {%1, %2};" : "=l"(r) : "r"(u), "r"(u)); return r;
}
__device__ __forceinline__ void unpack2(ull v, float& lo, float& hi) {
    unsigned a, b; asm("mov.b64 {%0, %1}, %2;" : "=r"(a), "=r"(b) : "l"(v));
    lo = __uint_as_float(a); hi = __uint_as_float(b);
}

// ---------------------------------------------------------------------------
// Kernel 1: split-half projection (R8, unchanged).
// ---------------------------------------------------------------------------
__global__ void proj_kernel(const float* __restrict__ f,
                            const float* __restrict__ W1,
                            const float* __restrict__ b1,
                            const float* __restrict__ W2) {
    __shared__ __align__(16) float w1s[64][64];
    __shared__ __align__(16) float fs[16][64];
    int tid = threadIdx.x;
    int half = blockIdx.y;
    const float* w1base = W1 + half * 64 * 64;
    for (int t = tid; t < 64 * 64 / 4; t += 256)
        ((float4*)w1s)[t] = ((const float4*)w1base)[t];
    int rowbase = blockIdx.x * 16;
    for (int t = tid; t < 16 * 64 / 4; t += 256)
        ((float4*)fs)[t] = ((const float4*)(f + rowbase * 64))[t];
    __syncthreads();

    int r = tid >> 4;
    int d0 = (tid & 15) * 4;
    float4 h = make_float4(0.f, 0.f, 0.f, 0.f);
#pragma unroll 8
    for (int k = 0; k < 64; ++k) {
        float fv = fs[r][k];
        float4 w = *(const float4*)&w1s[k][d0];
        h.x = fmaf(fv, w.x, h.x); h.y = fmaf(fv, w.y, h.y);
        h.z = fmaf(fv, w.z, h.z); h.w = fmaf(fv, w.w, h.w);
    }
    int row = rowbase + r;
    if (half) {
        float4 bb = *(const float4*)&b1[d0];
        h.x += bb.x; h.y += bb.y; h.z += bb.z; h.w += bb.w;
        *(float4*)&g_hd[row * 64 + d0] = h;
    } else {
        *(float4*)&g_hs[row * 64 + d0] = h;
    }

    float4 w2v = *(const float4*)&W2[d0];
    float pt = h.x * w2v.x + h.y * w2v.y + h.z * w2v.z + h.w * w2v.w;
#pragma unroll
    for (int m = 8; m >= 1; m >>= 1)
        pt += __shfl_xor_sync(0xffffffffu, pt, m);
    if ((tid & 15) == 0) {
        if (half) g_thd[row] = 0.25f * pt;
        else      g_ths[row] = 0.25f * pt;
    }
}

// ---------------------------------------------------------------------------
// Threefry2x32, key (0,42), 20 rounds; partitionable: bits = o0 ^ o1.
// ---------------------------------------------------------------------------
__device__ __forceinline__ uint32_t threefry_xor(uint32_t x0, uint32_t x1) {
    const uint32_t ks0 = 0u, ks1 = 42u, ks2 = 0x1BD11BDAu ^ 0u ^ 42u;
    x0 += ks0; x1 += ks1;
#define TF_RND(r) { x0 += x1; x1 = __funnelshift_l(x1, x1, (r)); x1 ^= x0; }
    TF_RND(13) TF_RND(15) TF_RND(26) TF_RND(6)   x0 += ks1; x1 += ks2 + 1u;
    TF_RND(17) TF_RND(29) TF_RND(16) TF_RND(24)  x0 += ks2; x1 += ks0 + 2u;
    TF_RND(13) TF_RND(15) TF_RND(26) TF_RND(6)   x0 += ks0; x1 += ks1 + 3u;
    TF_RND(17) TF_RND(29) TF_RND(16) TF_RND(24)  x0 += ks1; x1 += ks2 + 4u;
    TF_RND(13) TF_RND(15) TF_RND(26) TF_RND(6)   x0 += ks2; x1 += ks0 + 5u;
#undef TF_RND
    return x0 ^ x1;
}

__device__ __forceinline__ float u_from_bits(uint32_t bits) {
    float f = __uint_as_float((bits >> 9) | 0x3f800000u) - 1.0f;
    return fmaxf(f, 1.17549435e-38f);
}

// Cold precise path (validated in R6-R8): exp(sv)*E1 >= E0 with precise log/exp
__device__ __noinline__ bool precise_take(float sv, uint32_t L0) {
    float u0 = u_from_bits(threefry_xor(0u, L0));
    float u1 = u_from_bits(threefry_xor(0u, L0 + 1u));
    float E0 = -logf(u0);
    float E1 = -logf(u1);
    return expf(sv) * E1 >= E0;
}

// ---------------------------------------------------------------------------
// Fused kernel (persistent): units = (pair p, batch b).
// Mainloop (packed f32x2 abs-sum) interleaved with per-thread gumbel-threshold
// computation tau = log(E0)-log(E1) (threefry; alu pipe) so both pipes co-issue.
// Epilogue: sym logits + compare-vs-tau (fp16, guarded precise fallback).
// ---------------------------------------------------------------------------
struct MainSmem {
    ull  sAi[32][34];   // (hs_i, hs_i) packed, [d][row]
    ull  sAj[32][34];
    float sCi[32][36];  // hd_i [d][col]
    float sCj[32][36];
};
struct EpiSmem {
    float S1[32][36];
    float S2[32][36];
};
union FusedSmem { MainSmem m; EpiSmem e; };

__global__ __launch_bounds__(128, 7)
void fused_kernel(const float* __restrict__ W2,
                  const float* __restrict__ b2,
                  float* __restrict__ out) {
    __shared__ __align__(16) FusedSmem sm;
    __shared__ __align__(16) ull sW[64];    // (0.25*w2, 0.25*w2)
    __shared__ float stI[32], stJ[32];

    int tid = threadIdx.x;
    if (tid < 64) sW[tid] = pack2(0.25f * W2[tid]);
    float b2v = b2[0];
    float* adj = out;
    float* lg  = out + (size_t)NN;

    int grp = tid >> 6;
    int g = tid & 63;
    int r0 = (g >> 3) * 4, c0 = (g & 7) * 4;
    int ti = tid >> 2;
    int tj0 = (tid & 3) * 8;

    const ull ABSM = 0x7FFFFFFF7FFFFFFFull;

    for (int unit = blockIdx.x; unit < NUNITS; unit += gridDim.x) {
        int p = unit >> 2, b = unit & 3;
        // decode p -> (ib <= jb), p = jb*(jb+1)/2 + ib
        int jb = (int)((sqrtf(8.0f * (float)p + 1.0f) - 1.0f) * 0.5f);
        while (jb * (jb + 1) / 2 > p) --jb;
        while ((jb + 1) * (jb + 2) / 2 <= p) ++jb;
        int ib = p - jb * (jb + 1) / 2;

        __syncthreads();   // prev-unit epilogue reads of stI/stJ complete
        if (tid >= 64 && tid < 96) {
            int q = tid - 64;
            stI[q] = g_ths[b * N_ + ib * 32 + q] + g_thd[b * N_ + ib * 32 + q];
        }
        if (tid >= 96) {
            int q = tid - 96;
            stJ[q] = g_ths[b * N_ + jb * 32 + q] + g_thd[b * N_ + jb * 32 + q];
        }

        const float* hsI = g_hs + ((size_t)b * N_ + ib * 32) * 64;
        const float* hsJ = g_hs + ((size_t)b * N_ + jb * 32) * 64;
        const float* hdI = g_hd + ((size_t)b * N_ + ib * 32) * 64;
        const float* hdJ = g_hd + ((size_t)b * N_ + jb * 32) * 64;

        ull acc01[4], acc23[4];
#pragma unroll
        for (int r = 0; r < 4; ++r) { acc01[r] = 0ull; acc23[r] = 0ull; }

        uint32_t th8[2][4];   // fp16 tau, 8 per region, this thread's elements

#pragma unroll
        for (int kc = 0; kc < 2; ++kc) {
            __syncthreads();
            for (int t = tid; t < 256; t += 128) {
                int rr = t >> 3, q = (t & 7) * 4;
                float4 a1 = *(const float4*)&hsI[rr * 64 + kc * 32 + q];
                float4 a2 = *(const float4*)&hsJ[rr * 64 + kc * 32 + q];
                float4 c1 = *(const float4*)&hdI[rr * 64 + kc * 32 + q];
                float4 c2 = *(const float4*)&hdJ[rr * 64 + kc * 32 + q];
                sm.m.sAi[q + 0][rr] = pack2(a1.x); sm.m.sAi[q + 1][rr] = pack2(a1.y);
                sm.m.sAi[q + 2][rr] = pack2(a1.z); sm.m.sAi[q + 3][rr] = pack2(a1.w);
                sm.m.sAj[q + 0][rr] = pack2(a2.x); sm.m.sAj[q + 1][rr] = pack2(a2.y);
                sm.m.sAj[q + 2][rr] = pack2(a2.z); sm.m.sAj[q + 3][rr] = pack2(a2.w);
                sm.m.sCi[q + 0][rr] = c1.x; sm.m.sCi[q + 1][rr] = c1.y;
                sm.m.sCi[q + 2][rr] = c1.z; sm.m.sCi[q + 3][rr] = c1.w;
                sm.m.sCj[q + 0][rr] = c2.x; sm.m.sCj[q + 1][rr] = c2.y;
                sm.m.sCj[q + 2][rr] = c2.z; sm.m.sCj[q + 3][rr] = c2.w;
            }
            __syncthreads();

            const ull*  aB = grp ? &sm.m.sAj[0][0] : &sm.m.sAi[0][0];
            const float* cB = grp ? &sm.m.sCi[0][0] : &sm.m.sCj[0][0];

#pragma unroll 8
            for (int dd = 0; dd < 32; ++dd) {
                ull w = sW[kc * 32 + dd];
                ulonglong2 aa01 = *(const ulonglong2*)(aB + dd * 34 + r0);
                ulonglong2 aa23 = *(const ulonglong2*)(aB + dd * 34 + r0 + 2);
                ulonglong2 cc   = *(const ulonglong2*)(cB + dd * 36 + c0);
                ull x;
                x = add2(aa01.x, cc.x); acc01[0] = fma2(x & ABSM, w, acc01[0]);
                x = add2(aa01.x, cc.y); acc23[0] = fma2(x & ABSM, w, acc23[0]);
                x = add2(aa01.y, cc.x); acc01[1] = fma2(x & ABSM, w, acc01[1]);
                x = add2(aa01.y, cc.y); acc23[1] = fma2(x & ABSM, w, acc23[1]);
                x = add2(aa23.x, cc.x); acc01[2] = fma2(x & ABSM, w, acc01[2]);
                x = add2(aa23.x, cc.y); acc23[2] = fma2(x & ABSM, w, acc23[2]);
                x = add2(aa23.y, cc.x); acc01[3] = fma2(x & ABSM, w, acc01[3]);
                x = add2(aa23.y, cc.y); acc23[3] = fma2(x & ABSM, w, acc23[3]);
            }

            // ---- tau section (reg = kc): alu-heavy, independent of the fma
            // accumulation chains above -> scheduler interleaves both pipes.
            {
                int rowblk = kc ? jb : ib;
                int colblk = kc ? ib : jb;
                int i = rowblk * 32 + ti;
                uint32_t rowidx = ((uint32_t)(b * N_ + i)) * N_ + colblk * 32 + tj0;
#pragma unroll 2
                for (int c = 0; c < 8; ++c) {
                    uint32_t L0 = (rowidx + c) << 1;
                    float u0 = u_from_bits(threefry_xor(0u, L0));
                    float u1 = u_from_bits(threefry_xor(0u, L0 + 1u));
                    float tau = __logf(-__logf(u0)) - __logf(-__logf(u1));
                    __half h = __float2half_rn(tau);
                    ((__half*)&th8[kc][0])[c] = h;
                }
            }
        }
        __syncthreads();

        float* Sd = grp ? &sm.e.S2[0][0] : &sm.e.S1[0][0];
#pragma unroll
        for (int r = 0; r < 4; ++r) {
            float4 o;
            unpack2(acc01[r], o.x, o.y);
            unpack2(acc23[r], o.z, o.w);
            *(float4*)(Sd + (r0 + r) * 36 + c0) = o;
        }
        __syncthreads();

#pragma unroll
        for (int reg = 0; reg < 2; ++reg) {
            int rowblk = reg ? jb : ib;
            int colblk = reg ? ib : jb;
            const float* Sa = reg ? &sm.e.S2[0][0] : &sm.e.S1[0][0];
            const float* Sb = reg ? &sm.e.S1[0][0] : &sm.e.S2[0][0];
            const float* tR = reg ? stJ : stI;
            const float* tC = reg ? stI : stJ;
            int i = rowblk * 32 + ti;
            size_t rowidx = ((size_t)b * N_ + i) * N_ + colblk * 32;
            float tRv = tR[ti] + b2v;
            float4 lgv[2], adv[2];
#pragma unroll
            for (int c = 0; c < 8; ++c) {
                int tj = tj0 + c;
                float sv = tRv + tC[tj] + Sa[ti * 36 + tj] + Sb[tj * 36 + ti];
                float thr = __half2float(((const __half*)&th8[reg][0])[c]);
                bool take;
                float margin = fabsf(sv - thr);
                if (margin >= 0.02f + 0.002f * fabsf(thr)) {
                    take = sv >= thr;
                } else {
                    take = precise_take(sv, ((uint32_t)(rowidx + tj)) << 1);
                }
                int j = colblk * 32 + tj;
                float mask = (i == j) ? 0.f : 1.f;
                ((float*)lgv)[c] = sv;
                ((float*)adv)[c] = take ? mask : 0.f;
            }
            *(float4*)(lg + rowidx + tj0) = lgv[0];
            *(float4*)(lg + rowidx + tj0 + 4) = lgv[1];
            *(float4*)(adj + rowidx + tj0) = adv[0];
            *(float4*)(adj + rowidx + tj0 + 4) = adv[1];
        }
    }
}

// ---------------------------------------------------------------------------
extern "C" void kernel_launch(void* const* d_in, const int* in_sizes, int n_in,
                              void* d_out, int out_size) {
    const float* f  = (const float*)d_in[0];
    const float* W1 = (const float*)d_in[1];
    const float* b1 = (const float*)d_in[2];
    const float* W2 = (const float*)d_in[3];
    const float* b2 = (const float*)d_in[4];

    proj_kernel<<<dim3((B_ * N_) / 16, 2), 256>>>(f, W1, b1, W2);
    fused_kernel<<<148 * 7, 128>>>(W2, b2, (float*)d_out);
}

// round 10
// speedup vs baseline: 1.2483x; 1.2483x over previous
#include <cuda_runtime.h>
#include <stdint.h>

#define B_ 4
#define N_ 1024
#define D_ 64
#define NN (B_ * N_ * N_)

typedef unsigned long long ull;

// Scratch (device globals — no allocation allowed)
__device__ float g_hs[B_ * N_ * D_];
__device__ float g_hd[B_ * N_ * D_];
__device__ float g_tp[4][B_ * N_];   // t-partials: [half*2 + dhalf][node]

// ---------------------------------------------------------------------------
// f32x2 packed helpers (sm_103a)
// ---------------------------------------------------------------------------
__device__ __forceinline__ ull add2(ull a, ull b) {
    ull r; asm("add.rn.f32x2 %0, %1, %2;" : "=l"(r) : "l"(a), "l"(b)); return r;
}
__device__ __forceinline__ ull fma2(ull a, ull b, ull c) {
    ull r; asm("fma.rn.f32x2 %0, %1, %2, %3;" : "=l"(r) : "l"(a), "l"(b), "l"(c)); return r;
}
__device__ __forceinline__ ull pack2(float v) {
    ull r; unsigned u = __float_as_uint(v);
    asm("mov.b64 %0, {%1, %2};" : "=l"(r) : "r"(u), "r"(u)); return r;
}
__device__ __forceinline__ void unpack2(ull v, float& lo, float& hi) {
    unsigned a, b; asm("mov.b64 {%0, %1}, %2;" : "=r"(a), "=r"(b) : "l"(v));
    lo = __uint_as_float(a); hi = __uint_as_float(b);
}
__device__ __forceinline__ float lo32(ull v) {
    unsigned a, b; asm("mov.b64 {%0, %1}, %2;" : "=r"(a), "=r"(b) : "l"(v));
    return __uint_as_float(a);
}

// ---------------------------------------------------------------------------
// Kernel 1: projection, split by (W1 half, d-halfslice).
// grid (256, 2, 2): 16 rows/block, 128 threads = 16 rows x 8 d-quads.
// half=0: hs slice; half=1: hd slice (+b1). Stages 8KB W1 slice + f tile.
// ---------------------------------------------------------------------------
__global__ void proj_kernel(const float* __restrict__ f,
                            const float* __restrict__ W1,
                            const float* __restrict__ b1,
                            const float* __restrict__ W2) {
    __shared__ __align__(16) float w1s[64][32];
    __shared__ __align__(16) float fs[16][68];
    int tid = threadIdx.x;
    int half = blockIdx.y;
    int dh = blockIdx.z;
    const float* w1base = W1 + half * 64 * 64 + dh * 32;

    // stage W1 slice [64 k][32 c]
    for (int m = 0; m < 4; ++m) {
        int idx = tid + 128 * m;
        int k = idx >> 3, cq = (idx & 7) * 4;
        *(float4*)&w1s[k][cq] = *(const float4*)&w1base[k * 64 + cq];
    }
    // stage f tile [16 rows][64 k] (padded rows)
    int rowbase = blockIdx.x * 16;
    for (int m = 0; m < 2; ++m) {
        int idx = tid + 128 * m;
        int r = idx >> 4, kq = (idx & 15) * 4;
        *(float4*)&fs[r][kq] = *(const float4*)&f[(rowbase + r) * 64 + kq];
    }
    __syncthreads();

    int r = tid >> 3;
    int dq = (tid & 7) * 4;
    float4 h = make_float4(0.f, 0.f, 0.f, 0.f);
#pragma unroll 8
    for (int k = 0; k < 64; ++k) {
        float fv = fs[r][k];
        float4 w = *(const float4*)&w1s[k][dq];
        h.x = fmaf(fv, w.x, h.x); h.y = fmaf(fv, w.y, h.y);
        h.z = fmaf(fv, w.z, h.z); h.w = fmaf(fv, w.w, h.w);
    }
    int row = rowbase + r;
    int d0 = dh * 32 + dq;
    if (half) {
        float4 bb = *(const float4*)&b1[d0];
        h.x += bb.x; h.y += bb.y; h.z += bb.z; h.w += bb.w;
        *(float4*)&g_hd[row * 64 + d0] = h;
    } else {
        *(float4*)&g_hs[row * 64 + d0] = h;
    }

    float4 w2v = *(const float4*)&W2[d0];
    float pt = h.x * w2v.x + h.y * w2v.y + h.z * w2v.z + h.w * w2v.w;
#pragma unroll
    for (int m = 4; m >= 1; m >>= 1)
        pt += __shfl_xor_sync(0xffffffffu, pt, m);
    if ((tid & 7) == 0) g_tp[half * 2 + dh][row] = 0.25f * pt;
}

// ---------------------------------------------------------------------------
// Threefry2x32, key (0,42), 20 rounds; partitionable: bits = o0 ^ o1.
// ---------------------------------------------------------------------------
__device__ __forceinline__ uint32_t threefry_xor(uint32_t x0, uint32_t x1) {
    const uint32_t ks0 = 0u, ks1 = 42u, ks2 = 0x1BD11BDAu ^ 0u ^ 42u;
    x0 += ks0; x1 += ks1;
#define TF_RND(r) { x0 += x1; x1 = __funnelshift_l(x1, x1, (r)); x1 ^= x0; }
    TF_RND(13) TF_RND(15) TF_RND(26) TF_RND(6)   x0 += ks1; x1 += ks2 + 1u;
    TF_RND(17) TF_RND(29) TF_RND(16) TF_RND(24)  x0 += ks2; x1 += ks0 + 2u;
    TF_RND(13) TF_RND(15) TF_RND(26) TF_RND(6)   x0 += ks0; x1 += ks1 + 3u;
    TF_RND(17) TF_RND(29) TF_RND(16) TF_RND(24)  x0 += ks1; x1 += ks2 + 4u;
    TF_RND(13) TF_RND(15) TF_RND(26) TF_RND(6)   x0 += ks2; x1 += ks0 + 5u;
#undef TF_RND
    return x0 ^ x1;
}

__device__ __forceinline__ float u_from_bits(uint32_t bits) {
    float f = __uint_as_float((bits >> 9) | 0x3f800000u) - 1.0f;
    return fmaxf(f, 1.17549435e-38f);
}

// ---------------------------------------------------------------------------
// Fused kernel (R8 structure): tile pair (ib<=jb), 32x32 each.
//   S = sum_d 0.25*w|hs_i + hd_j| ; sym = t_i + t_j + b2 + S1[i][j] + S2[j][i]
// Epilogue: phase-split gumbel (all threefry chains first, then logs/compare).
// ---------------------------------------------------------------------------
struct MainSmem {
    ull  sAi[32][34];   // (hs_i, hs_i) packed, [d][row]
    ull  sAj[32][34];
    float sCi[32][36];  // hd_i [d][col]
    float sCj[32][36];
};
struct EpiSmem {
    float S1[32][36];
    float S2[32][36];
};
union FusedSmem { MainSmem m; EpiSmem e; };

__global__ __launch_bounds__(128, 8)
void fused_kernel(const float* __restrict__ W2,
                  const float* __restrict__ b2,
                  float* __restrict__ out) {
    __shared__ __align__(16) FusedSmem sm;
    __shared__ __align__(16) ull sW[64];    // (0.25*w2, 0.25*w2)
    __shared__ float stI[32], stJ[32];

    int tid = threadIdx.x;
    int b = blockIdx.y;
    int p = blockIdx.x;
    // decode p -> (ib <= jb), p = jb*(jb+1)/2 + ib
    int jb = (int)((sqrtf(8.0f * (float)p + 1.0f) - 1.0f) * 0.5f);
    while (jb * (jb + 1) / 2 > p) --jb;
    while ((jb + 1) * (jb + 2) / 2 <= p) ++jb;
    int ib = p - jb * (jb + 1) / 2;

    if (tid < 64) sW[tid] = pack2(0.25f * W2[tid]);
    if (tid >= 64 && tid < 96) {
        int q = tid - 64, n = b * N_ + ib * 32 + q;
        stI[q] = g_tp[0][n] + g_tp[1][n] + g_tp[2][n] + g_tp[3][n];
    }
    if (tid >= 96) {
        int q = tid - 96, n = b * N_ + jb * 32 + q;
        stJ[q] = g_tp[0][n] + g_tp[1][n] + g_tp[2][n] + g_tp[3][n];
    }

    const float* hsI = g_hs + ((size_t)b * N_ + ib * 32) * 64;
    const float* hsJ = g_hs + ((size_t)b * N_ + jb * 32) * 64;
    const float* hdI = g_hd + ((size_t)b * N_ + ib * 32) * 64;
    const float* hdJ = g_hd + ((size_t)b * N_ + jb * 32) * 64;

    int grp = tid >> 6;
    int g = tid & 63;
    int r0 = (g >> 3) * 4, c0 = (g & 7) * 4;

    ull acc01[4], acc23[4];
#pragma unroll
    for (int r = 0; r < 4; ++r) { acc01[r] = 0ull; acc23[r] = 0ull; }

    const ull ABSM = 0x7FFFFFFF7FFFFFFFull;

    for (int kc = 0; kc < 2; ++kc) {
        __syncthreads();
        for (int t = tid; t < 256; t += 128) {
            int rr = t >> 3, q = (t & 7) * 4;
            float4 a1 = *(const float4*)&hsI[rr * 64 + kc * 32 + q];
            float4 a2 = *(const float4*)&hsJ[rr * 64 + kc * 32 + q];
            float4 c1 = *(const float4*)&hdI[rr * 64 + kc * 32 + q];
            float4 c2 = *(const float4*)&hdJ[rr * 64 + kc * 32 + q];
            sm.m.sAi[q + 0][rr] = pack2(a1.x); sm.m.sAi[q + 1][rr] = pack2(a1.y);
            sm.m.sAi[q + 2][rr] = pack2(a1.z); sm.m.sAi[q + 3][rr] = pack2(a1.w);
            sm.m.sAj[q + 0][rr] = pack2(a2.x); sm.m.sAj[q + 1][rr] = pack2(a2.y);
            sm.m.sAj[q + 2][rr] = pack2(a2.z); sm.m.sAj[q + 3][rr] = pack2(a2.w);
            sm.m.sCi[q + 0][rr] = c1.x; sm.m.sCi[q + 1][rr] = c1.y;
            sm.m.sCi[q + 2][rr] = c1.z; sm.m.sCi[q + 3][rr] = c1.w;
            sm.m.sCj[q + 0][rr] = c2.x; sm.m.sCj[q + 1][rr] = c2.y;
            sm.m.sCj[q + 2][rr] = c2.z; sm.m.sCj[q + 3][rr] = c2.w;
        }
        __syncthreads();

        const ull*  aB = grp ? &sm.m.sAj[0][0] : &sm.m.sAi[0][0];
        const float* cB = grp ? &sm.m.sCi[0][0] : &sm.m.sCj[0][0];

#pragma unroll 8
        for (int dd = 0; dd < 32; ++dd) {
            ull w = sW[kc * 32 + dd];
            ulonglong2 aa01 = *(const ulonglong2*)(aB + dd * 34 + r0);
            ulonglong2 aa23 = *(const ulonglong2*)(aB + dd * 34 + r0 + 2);
            ulonglong2 cc   = *(const ulonglong2*)(cB + dd * 36 + c0);
            ull x;
            x = add2(aa01.x, cc.x); acc01[0] = fma2(x & ABSM, w, acc01[0]);
            x = add2(aa01.x, cc.y); acc23[0] = fma2(x & ABSM, w, acc23[0]);
            x = add2(aa01.y, cc.x); acc01[1] = fma2(x & ABSM, w, acc01[1]);
            x = add2(aa01.y, cc.y); acc23[1] = fma2(x & ABSM, w, acc23[1]);
            x = add2(aa23.x, cc.x); acc01[2] = fma2(x & ABSM, w, acc01[2]);
            x = add2(aa23.x, cc.y); acc23[2] = fma2(x & ABSM, w, acc23[2]);
            x = add2(aa23.y, cc.x); acc01[3] = fma2(x & ABSM, w, acc01[3]);
            x = add2(aa23.y, cc.y); acc23[3] = fma2(x & ABSM, w, acc23[3]);
        }
    }
    __syncthreads();

    float* Sd = grp ? &sm.e.S2[0][0] : &sm.e.S1[0][0];
#pragma unroll
    for (int r = 0; r < 4; ++r) {
        float4 o;
        unpack2(acc01[r], o.x, o.y);
        unpack2(acc23[r], o.z, o.w);
        *(float4*)(Sd + (r0 + r) * 36 + c0) = o;
    }
    __syncthreads();

    float b2v = b2[0];
    float* adj = out;
    float* lg  = out + (size_t)NN;

    int ti = tid >> 2;
    int tj0 = (tid & 3) * 8;

#pragma unroll 1
    for (int reg = 0; reg < 2; ++reg) {
        int rowblk = reg ? jb : ib;
        int colblk = reg ? ib : jb;
        const float* Sa = reg ? &sm.e.S2[0][0] : &sm.e.S1[0][0];
        const float* Sb = reg ? &sm.e.S1[0][0] : &sm.e.S2[0][0];
        const float* tR = reg ? stJ : stI;
        const float* tC = reg ? stI : stJ;
        int i = rowblk * 32 + ti;
        size_t rowidx = ((size_t)b * N_ + i) * N_ + colblk * 32;
        float tRv = tR[ti] + b2v;

        // phase 1: all 16 threefry chains in flight
        float u0a[8], u1a[8];
#pragma unroll
        for (int c = 0; c < 8; ++c) {
            uint32_t L0 = ((uint32_t)(rowidx + tj0 + c)) << 1;
            u0a[c] = u_from_bits(threefry_xor(0u, L0));
            u1a[c] = u_from_bits(threefry_xor(0u, L0 + 1u));
        }

        // phase 2: logits + decision + write
        float4 lgv[2], adv[2];
#pragma unroll
        for (int c = 0; c < 8; ++c) {
            int tj = tj0 + c;
            float sv = tRv + tC[tj] + Sa[ti * 36 + tj] + Sb[tj * 36 + ti];
            float E0 = -__logf(u0a[c]);
            float E1 = -__logf(u1a[c]);
            float lhs = __expf(sv) * E1;
            bool take;
            float margin = fabsf(lhs - E0);
            if (margin >= 1e-4f * (lhs + E0)) {
                take = lhs >= E0;
            } else {
                float E0p = -logf(u0a[c]);
                float E1p = -logf(u1a[c]);
                take = expf(sv) * E1p >= E0p;
            }
            int j = colblk * 32 + tj;
            float mask = (i == j) ? 0.f : 1.f;
            ((float*)lgv)[c] = sv;
            ((float*)adv)[c] = take ? mask : 0.f;
        }
        *(float4*)(lg + rowidx + tj0) = lgv[0];
        *(float4*)(lg + rowidx + tj0 + 4) = lgv[1];
        *(float4*)(adj + rowidx + tj0) = adv[0];
        *(float4*)(adj + rowidx + tj0 + 4) = adv[1];
    }
}

// ---------------------------------------------------------------------------
extern "C" void kernel_launch(void* const* d_in, const int* in_sizes, int n_in,
                              void* d_out, int out_size) {
    const float* f  = (const float*)d_in[0];
    const float* W1 = (const float*)d_in[1];
    const float* b1 = (const float*)d_in[2];
    const float* W2 = (const float*)d_in[3];
    const float* b2 = (const float*)d_in[4];

    proj_kernel<<<dim3((B_ * N_) / 16, 2, 2), 128>>>(f, W1, b1, W2);
    int npairs = (N_ / 32) * (N_ / 32 + 1) / 2;  // 528
    fused_kernel<<<dim3(npairs, B_), 128>>>(W2, b2, (float*)d_out);
}